// round 16
// baseline (speedup 1.0000x reference)
#include <cuda_runtime.h>
#include <cstdint>

#define MAXB   64
#define MAXN   16
#define NC     21
#define MTPB   256
#define MPPT   3
#define MROWS  (MTPB*MPPT)      // 768
#define NABLK  32
#define MAXPP  24576
#define LTILE  192
#define LROWS  1152
#define NSB    8                // select slice-blocks per batch

// -------- scratch (__device__ globals; overwritten every launch) ----------
__device__ int                g_matchv[MAXB * MAXPP];
__device__ float              g_mine  [MAXB * MAXPP];
__device__ unsigned long long g_cK[MAXB * NABLK * MAXN];
__device__ float              g_corrL[MAXB], g_corrC[MAXB];
__device__ int                g_corrN[MAXB];
__device__ float              g_partL[MAXB * NSB], g_partC[MAXB * NSB];
__device__ int                g_partN[MAXB * NSB];
__device__ int                g_ghist[MAXB * 1024];   // zeroed by k_fused
__device__ int                g_fhist[MAXB * 1024];   // zeroed by k_fused
__device__ float              g_fsum [MAXB * 1024];   // zeroed by k_fused
__device__ int                g_Bs[MAXB], g_krem[MAXB];
__device__ float              g_c0[MAXB];
__device__ float              g_aS[MAXB * NSB];
__device__ float              g_bl[MAXB], g_bc[MAXB];
__device__ int                g_bn[MAXB];

__device__ __forceinline__ float smooth_l1(float d) {
    float ad = fabsf(d);
    return (ad < 1.0f) ? 0.5f * d * d : ad - 0.5f;
}

__device__ __forceinline__ void cp16(float* dst, const float4* src) {
    unsigned s = (unsigned)__cvta_generic_to_shared(dst);
    asm volatile("cp.async.cg.shared.global [%0], [%1], 16;\n" :: "r"(s), "l"(src));
}

// ==========================================================================
// Fused: blockIdx.x < nA -> IoU matching (ALU); else -> lse stream (DRAM).
// MPPT=3 lowers natural reg pressure so the 6-block cap doesn't spill;
// LTILE=192 double-buffered keeps smem at 32.3 KB (6 blocks/SM).
__global__ __launch_bounds__(256, 6) void k_fused(
    const float* __restrict__ conf,
    const float* __restrict__ priors,
    const float* __restrict__ truths,
    int P, int N, int nA)
{
    __shared__ __align__(16) float s_conf[2 * LTILE * NC];   // 32.3 KB
    __shared__ float4 s_t[MAXN];
    __shared__ float  s_area[MAXN];
    __shared__ unsigned long long s_best[MAXN];

    int b   = blockIdx.y;
    int tid = threadIdx.x;

    if (blockIdx.x < 16 && tid < 64) {
        int base = b * 1024 + blockIdx.x * 64 + tid;
        g_ghist[base] = 0;
        g_fhist[base] = 0;
        g_fsum [base] = 0.f;
    }

    if (blockIdx.x < nA) {
        // ================= MATCH PATH =================
        int p0   = blockIdx.x * MROWS;
        int lane = tid & 31;

        if (tid < MAXN) {
            s_best[tid] = 0ULL;
            if (tid < N) {
                float4 t = reinterpret_cast<const float4*>(truths)[b * N + tid];
                s_t[tid] = t;
                s_area[tid] = (t.z - t.x) * (t.w - t.y);
            }
        }
        __syncthreads();

        float px1[MPPT], py1[MPPT], px2[MPPT], py2[MPPT], ab[MPPT];
        #pragma unroll
        for (int i = 0; i < MPPT; ++i) {
            int p  = p0 + i * MTPB + tid;
            int pc = min(p, P - 1);         // clamp; dups lose ties via ~p
            float4 pr = reinterpret_cast<const float4*>(priors)[pc];
            float hx = pr.z * 0.5f, hy = pr.w * 0.5f;
            px1[i] = pr.x - hx; py1[i] = pr.y - hy;
            px2[i] = pr.x + hx; py2[i] = pr.y + hy;
            ab[i]  = pr.z * pr.w;
        }

        float bt[MPPT];
        int   bn[MPPT];
        #pragma unroll
        for (int i = 0; i < MPPT; ++i) { bt[i] = -1.f; bn[i] = 0; }

        #pragma unroll
        for (int n = 0; n < MAXN; ++n) {
            if (n < N) {
                float4 t = s_t[n];
                float sa = s_area[n];
                float biou = -1.f;
                int   bp   = 0x7FFFFFFF;
                #pragma unroll
                for (int i = 0; i < MPPT; ++i) {
                    float w = __saturatef(fminf(t.z, px2[i]) - fmaxf(t.x, px1[i]));
                    float h = __saturatef(fminf(t.w, py2[i]) - fmaxf(t.y, py1[i]));
                    float inter = w * h;
                    float uni   = sa + ab[i] - inter;
                    float iou   = __fdividef(inter, uni);
                    if (iou > bt[i]) { bt[i] = iou; bn[i] = n; }
                    if (iou > biou)  { biou = iou; bp = p0 + i * MTPB + tid; }
                }
                unsigned long long key =
                    ((unsigned long long)__float_as_uint(fmaxf(biou, 0.f)) << 32)
                    | (unsigned)~bp;
                #pragma unroll
                for (int o = 16; o; o >>= 1) {
                    unsigned long long ok = __shfl_down_sync(0xFFFFFFFFu, key, o);
                    key = (ok > key) ? ok : key;
                }
                if (lane == 0) atomicMax(&s_best[n], key);
            }
        }

        #pragma unroll
        for (int i = 0; i < MPPT; ++i) {
            int p = p0 + i * MTPB + tid;
            if (p < P) {
                int pos = (bt[i] >= 0.5f) ? 1 : 0;
                g_matchv[(size_t)b * P + p] = bn[i] | (pos << 31);
            }
        }
        __syncthreads();
        if (tid < MAXN)
            g_cK[((size_t)b * NABLK + blockIdx.x) * MAXN + tid] = s_best[tid];

    } else {
        // ================= LSE PATH (double-buffered) =================
        int bx   = blockIdx.x - nA;
        int r0   = bx * LROWS;
        int rows = min(LROWS, P - r0);
        int nt   = (rows + LTILE - 1) / LTILE;

        auto stage = [&](int t) {
            int tr = min(LTILE, rows - t * LTILE);
            int total = tr * NC;
            int n4 = total >> 2;
            const float* srcf = conf + ((size_t)b * P + r0 + t * LTILE) * NC;
            const float4* src4 = reinterpret_cast<const float4*>(srcf);
            float* dst = s_conf + (t & 1) * (LTILE * NC);
            for (int i = tid; i < n4; i += MTPB) cp16(dst + i * 4, src4 + i);
            for (int i = (n4 << 2) + tid; i < total; i += MTPB) dst[i] = srcf[i];
            asm volatile("cp.async.commit_group;\n");
        };

        stage(0);
        for (int t = 0; t < nt; ++t) {
            if (t + 1 < nt) {
                stage(t + 1);
                asm volatile("cp.async.wait_group 1;\n");
            } else {
                asm volatile("cp.async.wait_group 0;\n");
            }
            __syncthreads();

            int r = t * LTILE + tid;
            if (tid < LTILE && r < rows) {
                const float* row = s_conf + (t & 1) * (LTILE * NC) + tid * NC;
                float e0 = 0.f, e1 = 0.f, e2 = 0.f, e3 = 0.f;
                #pragma unroll
                for (int c = 0; c < NC; c += 4) {
                    e0 += __expf(row[c]);
                    if (c + 1 < NC) e1 += __expf(row[c + 1]);
                    if (c + 2 < NC) e2 += __expf(row[c + 2]);
                    if (c + 3 < NC) e3 += __expf(row[c + 3]);
                }
                float lse = __logf((e0 + e1) + (e2 + e3));
                g_mine[(size_t)b * P + r0 + r] = lse - row[0];   // >= 0
            }
            __syncthreads();
        }
    }
}

// ==========================================================================
// k_force: per batch (1 warp) resolve forced priors, accumulate corrections,
// zero g_mine/g_matchv at forced priors (before any binning happens).
__global__ void k_force(
    const float* __restrict__ loc,
    const float* __restrict__ conf,
    const float* __restrict__ priors,
    const float* __restrict__ truths,
    const int*   __restrict__ labels,
    int P, int N, int nA)
{
    int b = blockIdx.x, lane = threadIdx.x;

    unsigned long long best = 0ULL;
    if (lane < N)
        for (int j = 0; j < nA; ++j) {
            unsigned long long k2 = g_cK[((size_t)b * NABLK + j) * MAXN + lane];
            best = (k2 > best) ? k2 : best;
        }
    int fp = (lane < N) ? (int)~(unsigned)best : -1;
    bool valid = (lane < N);
    #pragma unroll
    for (int m = 0; m < MAXN; ++m) {
        int pm = __shfl_sync(0xFFFFFFFFu, fp, m);
        if (m < N && m > lane && pm == fp) valid = false;   // last truth wins
    }
    float dL = 0.f, dC = 0.f; int dN = 0;
    if (valid) {
        int p = fp;
        const float* crow = conf + ((size_t)b * P + p) * NC;
        float lse = g_mine[(size_t)b * P + p] + crow[0];
        float4 pr = reinterpret_cast<const float4*>(priors)[p];
        float4 ld = reinterpret_cast<const float4*>(loc)[(size_t)b * P + p];
        float4 tt = reinterpret_cast<const float4*>(truths)[b * N + lane];
        dC += lse - crow[labels[b * N + lane] + 1];
        float gx = __fdividef((tt.x + tt.z) * 0.5f - pr.x, 0.1f * pr.z);
        float gy = __fdividef((tt.y + tt.w) * 0.5f - pr.y, 0.1f * pr.w);
        float gw = __logf(__fdividef(tt.z - tt.x, pr.z)) * 5.0f;
        float gh = __logf(__fdividef(tt.w - tt.y, pr.w)) * 5.0f;
        dL += smooth_l1(ld.x - gx) + smooth_l1(ld.y - gy)
            + smooth_l1(ld.z - gw) + smooth_l1(ld.w - gh);
        dN += 1;
        g_mine  [(size_t)b * P + p] = 0.f;
        g_matchv[(size_t)b * P + p] = 0;
    }
    #pragma unroll
    for (int o = 16; o; o >>= 1) {
        dL += __shfl_down_sync(0xFFFFFFFFu, dL, o);
        dC += __shfl_down_sync(0xFFFFFFFFu, dC, o);
        dN += __shfl_down_sync(0xFFFFFFFFu, dN, o);
    }
    if (lane == 0) { g_corrL[b] = dL; g_corrC[b] = dC; g_corrN[b] = dN; }
}

// ==========================================================================
// k_hist: 8 slice-blocks per batch. Positives -> partials + zero + writeback;
// every value binned (bits>>21) into per-warp uint16 hist. UNIFORM trip count
// so all 32 lanes execute every collective; validity via ballot mask.
__global__ __launch_bounds__(256) void k_hist(
    const float* __restrict__ loc,
    const float* __restrict__ conf,
    const float* __restrict__ priors,
    const float* __restrict__ truths,
    const int*   __restrict__ labels,
    int P, int N)
{
    int b = blockIdx.y, s = blockIdx.x, tid = threadIdx.x;
    int w = tid >> 5, lane = tid & 31;

    __shared__ unsigned short s_h16[8 * 1024];   // 16 KB per-warp hists
    __shared__ float4 s_t[MAXN];
    __shared__ int    s_lab[MAXN];
    __shared__ float  s_rL[8], s_rC[8];
    __shared__ int    s_rN[8];

    if (tid < N) {
        s_t[tid]   = reinterpret_cast<const float4*>(truths)[b * N + tid];
        s_lab[tid] = labels[b * N + tid];
    }
    {
        unsigned* z = reinterpret_cast<unsigned*>(s_h16);
        #pragma unroll
        for (int i = 0; i < 16; ++i) z[tid + i * 256] = 0u;
    }
    __syncthreads();

    int n4 = P >> 2;
    int S4 = (n4 + NSB - 1) / NSB;
    int j0 = s * S4;
    int j1 = min(j0 + S4, n4);
    int iters = (j1 - j0 + 255) / 256;

    const float4* mv  = reinterpret_cast<const float4*>(g_mine   + (size_t)b * P);
    const int4*   mm4 = reinterpret_cast<const int4*>  (g_matchv + (size_t)b * P);
    float4*       mw  = reinterpret_cast<float4*>      (g_mine   + (size_t)b * P);

    float L = 0.f, C = 0.f; int n = 0;
    unsigned short* myh = s_h16 + w * 1024;

    auto do_pos = [&](int mm, float& vref, int p, bool& chg) {
        if (mm < 0) {
            int bnn = mm & 0x7FFFFFFF;
            const float* crow = conf + ((size_t)b * P + p) * NC;
            float lse = vref + crow[0];
            C += lse - crow[s_lab[bnn] + 1];
            n++;
            float4 tt = s_t[bnn];
            float4 pr = reinterpret_cast<const float4*>(priors)[p];
            float gx = __fdividef((tt.x + tt.z) * 0.5f - pr.x, 0.1f * pr.z);
            float gy = __fdividef((tt.y + tt.w) * 0.5f - pr.y, 0.1f * pr.w);
            float gw = __logf(__fdividef(tt.z - tt.x, pr.z)) * 5.0f;
            float gh = __logf(__fdividef(tt.w - tt.y, pr.w)) * 5.0f;
            float4 ld = reinterpret_cast<const float4*>(loc)[(size_t)b * P + p];
            L += smooth_l1(ld.x - gx) + smooth_l1(ld.y - gy)
               + smooth_l1(ld.z - gw) + smooth_l1(ld.w - gh);
            vref = 0.f;
            chg = true;
        }
    };

    for (int i = 0; i < iters; ++i) {
        int j = j0 + i * 256 + tid;
        bool ok = (j < j1);
        float4 v = ok ? mv[j] : make_float4(0.f, 0.f, 0.f, 0.f);
        int4 m = ok ? mm4[j] : make_int4(0, 0, 0, 0);
        bool chg = false;
        int p = 4 * j;
        if (ok) {
            do_pos(m.x, v.x, p, chg);
            do_pos(m.y, v.y, p + 1, chg);
            do_pos(m.z, v.z, p + 2, chg);
            do_pos(m.w, v.w, p + 3, chg);
            if (chg) mw[j] = v;
        }
        unsigned vm = __ballot_sync(0xFFFFFFFFu, ok);
        {
            unsigned bin = __float_as_uint(v.x) >> 21;
            unsigned mk = __match_any_sync(0xFFFFFFFFu, bin) & vm;
            if (ok && lane == (__ffs(mk) - 1)) myh[bin] = (unsigned short)(myh[bin] + __popc(mk));
        }
        {
            unsigned bin = __float_as_uint(v.y) >> 21;
            unsigned mk = __match_any_sync(0xFFFFFFFFu, bin) & vm;
            if (ok && lane == (__ffs(mk) - 1)) myh[bin] = (unsigned short)(myh[bin] + __popc(mk));
        }
        {
            unsigned bin = __float_as_uint(v.z) >> 21;
            unsigned mk = __match_any_sync(0xFFFFFFFFu, bin) & vm;
            if (ok && lane == (__ffs(mk) - 1)) myh[bin] = (unsigned short)(myh[bin] + __popc(mk));
        }
        {
            unsigned bin = __float_as_uint(v.w) >> 21;
            unsigned mk = __match_any_sync(0xFFFFFFFFu, bin) & vm;
            if (ok && lane == (__ffs(mk) - 1)) myh[bin] = (unsigned short)(myh[bin] + __popc(mk));
        }
    }
    int tail = P & 3;
    if (s == NSB - 1 && tid < tail) {
        int p = (P & ~3) + tid;
        float vex = g_mine[(size_t)b * P + p];
        bool chg = false;
        do_pos(g_matchv[(size_t)b * P + p], vex, p, chg);
        if (chg) g_mine[(size_t)b * P + p] = 0.f;
        atomicAdd(&g_ghist[b * 1024 + (int)(__float_as_uint(vex) >> 21)], 1);
    }

    #pragma unroll
    for (int o = 16; o; o >>= 1) {
        L += __shfl_down_sync(0xFFFFFFFFu, L, o);
        C += __shfl_down_sync(0xFFFFFFFFu, C, o);
        n += __shfl_down_sync(0xFFFFFFFFu, n, o);
    }
    if (lane == 0) { s_rL[w] = L; s_rC[w] = C; s_rN[w] = n; }
    __syncthreads();
    if (tid == 0) {
        float Lt = 0.f, Ct = 0.f; int nt = 0;
        #pragma unroll
        for (int i = 0; i < 8; ++i) { Lt += s_rL[i]; Ct += s_rC[i]; nt += s_rN[i]; }
        g_partL[b * NSB + s] = Lt;
        g_partC[b * NSB + s] = Ct;
        g_partN[b * NSB + s] = nt;
    }

    {
        const unsigned* h32 = reinterpret_cast<const unsigned*>(s_h16);
        unsigned c0 = 0, c1 = 0, c2 = 0, c3 = 0;
        #pragma unroll
        for (int w2 = 0; w2 < 8; ++w2) {
            unsigned a = h32[w2 * 512 + 2 * tid];
            unsigned d = h32[w2 * 512 + 2 * tid + 1];
            c0 += a & 0xFFFFu; c1 += a >> 16;
            c2 += d & 0xFFFFu; c3 += d >> 16;
        }
        int base = b * 1024 + 4 * tid;
        if (c0) atomicAdd(&g_ghist[base],     (int)c0);
        if (c1) atomicAdd(&g_ghist[base + 1], (int)c1);
        if (c2) atomicAdd(&g_ghist[base + 2], (int)c2);
        if (c3) atomicAdd(&g_ghist[base + 3], (int)c3);
    }
}

// ==========================================================================
// 1024-bin suffix scan (512 threads, 2 bins/thread).
__device__ __forceinline__ void find_thresh1024(
    int l0, int l1, int k, int tid, int* s_wt, int* s_out)
{
    int w = tid >> 5, lane = tid & 31;
    int loc = l0 + l1;
    int incl = loc;
    #pragma unroll
    for (int o = 1; o < 32; o <<= 1) {
        int x = __shfl_up_sync(0xFFFFFFFFu, incl, o);
        if (lane >= o) incl += x;
    }
    int wsum = __shfl_sync(0xFFFFFFFFu, incl, 31);
    if (lane == 31) s_wt[w] = wsum;
    __syncthreads();
    int wa = 0;
    #pragma unroll
    for (int w2 = 0; w2 < 16; ++w2) if (w2 > w) wa += s_wt[w2];
    int above = wa + (wsum - incl);
    if (above < k && above + loc >= k) {
        if (above + l1 >= k) { s_out[0] = 2 * tid + 1; s_out[1] = above; }
        else                 { s_out[0] = 2 * tid;     s_out[1] = above + l1; }
    }
    __syncthreads();
}

// ==========================================================================
// k_pick: per batch — finalize partials, coarse threshold bin (512 threads,
// the R12-measured-faster config).
__global__ __launch_bounds__(512) void k_pick(int P) {
    int b = blockIdx.x, tid = threadIdx.x;
    int w = tid >> 5, lane = tid & 31;

    __shared__ int s_wt[16];
    __shared__ int s_out[2];
    __shared__ int s_k;

    if (tid == 0) { s_out[0] = 0; s_out[1] = 0; }
    if (w == 0) {
        float L = 0.f, C = 0.f; int n = 0;
        if (lane < NSB) {
            L = g_partL[b * NSB + lane];
            C = g_partC[b * NSB + lane];
            n = g_partN[b * NSB + lane];
        } else if (lane == NSB) {
            L = g_corrL[b]; C = g_corrC[b]; n = g_corrN[b];
        }
        #pragma unroll
        for (int o = 16; o; o >>= 1) {
            L += __shfl_down_sync(0xFFFFFFFFu, L, o);
            C += __shfl_down_sync(0xFFFFFFFFu, C, o);
            n += __shfl_down_sync(0xFFFFFFFFu, n, o);
        }
        if (lane == 0) {
            g_bl[b] = L; g_c0[b] = C; g_bn[b] = n;
            s_k = (n > 0) ? min(3 * n, P - 1) : 0;
        }
    }
    __syncthreads();
    int k = s_k;

    int l0 = g_ghist[b * 1024 + 2 * tid];
    int l1 = g_ghist[b * 1024 + 2 * tid + 1];
    find_thresh1024(l0, l1, k, tid, s_wt, s_out);

    if (tid == 0) {
        if (k > 0) { g_Bs[b] = s_out[0]; g_krem[b] = k - s_out[1]; }
        else       { g_Bs[b] = 1024;     g_krem[b] = 0; }
    }
}

// ==========================================================================
// k_fine: 8 slice-blocks per batch. Exact sum of values above coarse bin;
// tie-bin values get fine count + sum via gmem atomics.
__global__ __launch_bounds__(256) void k_fine(int P) {
    int b = blockIdx.y, s = blockIdx.x, tid = threadIdx.x;
    int w = tid >> 5, lane = tid & 31;

    __shared__ float s_r[8];

    int Bs = g_Bs[b];
    int n4 = P >> 2;
    int S4 = (n4 + NSB - 1) / NSB;
    int j0 = s * S4;
    int j1 = min(j0 + S4, n4);

    const float4* mv = reinterpret_cast<const float4*>(g_mine + (size_t)b * P);
    float S = 0.f;

    auto proc = [&](float v) {
        int bin = (int)(__float_as_uint(v) >> 21);
        if (bin > Bs) {
            S += v;
        } else if (bin == Bs) {
            int fb = (int)((__float_as_uint(v) >> 11) & 1023u);
            atomicAdd(&g_fhist[b * 1024 + fb], 1);
            atomicAdd(&g_fsum [b * 1024 + fb], v);
        }
    };

    for (int j = j0 + tid; j < j1; j += 256) {
        float4 v = mv[j];
        proc(v.x); proc(v.y); proc(v.z); proc(v.w);
    }
    int tail = P & 3;
    if (s == NSB - 1 && tid < tail)
        proc(g_mine[(size_t)b * P + (P & ~3) + tid]);

    #pragma unroll
    for (int o = 16; o; o >>= 1) S += __shfl_down_sync(0xFFFFFFFFu, S, o);
    if (lane == 0) s_r[w] = S;
    __syncthreads();
    if (tid == 0) {
        float T = 0.f;
        #pragma unroll
        for (int i = 0; i < 8; ++i) T += s_r[i];
        g_aS[b * NSB + s] = T;
    }
}

// ==========================================================================
// k_batch: per batch — fine threshold, tie term via bin mean, total loss_c.
__global__ __launch_bounds__(512) void k_batch(int P) {
    int b = blockIdx.x, tid = threadIdx.x;
    int w = tid >> 5, lane = tid & 31;

    __shared__ int   s_wt[16];
    __shared__ int   s_out[2];
    __shared__ float s_r[16];
    __shared__ float s_above;
    __shared__ int   s_krem;

    if (w == 0) {
        float a = (lane < NSB) ? g_aS[b * NSB + lane] : 0.f;
        #pragma unroll
        for (int o = 16; o; o >>= 1) a += __shfl_down_sync(0xFFFFFFFFu, a, o);
        if (lane == 0) {
            s_above = a;
            s_krem  = g_krem[b];
            s_out[0] = 0; s_out[1] = 0;
        }
    }
    __syncthreads();
    int krem = s_krem;

    int l0 = g_fhist[b * 1024 + 2 * tid];
    int l1 = g_fhist[b * 1024 + 2 * tid + 1];
    find_thresh1024(l0, l1, krem, tid, s_wt, s_out);
    int Ss = s_out[0];
    int c2 = s_out[1];

    float fs = 0.f;
    if (krem > 0) {
        if (2 * tid     > Ss) fs += g_fsum[b * 1024 + 2 * tid];
        if (2 * tid + 1 > Ss) fs += g_fsum[b * 1024 + 2 * tid + 1];
    }
    #pragma unroll
    for (int o = 16; o; o >>= 1) fs += __shfl_down_sync(0xFFFFFFFFu, fs, o);
    if (lane == 0) s_r[w] = fs;
    __syncthreads();

    if (tid == 0) {
        float FS = 0.f;
        #pragma unroll
        for (int i = 0; i < 16; ++i) FS += s_r[i];
        float bc = g_c0[b];
        if (krem > 0) {
            int   hS = g_fhist[b * 1024 + Ss];
            float sS = g_fsum [b * 1024 + Ss];
            int  rem = krem - c2;
            float tie = (hS > 0) ? (float)rem * (sS / (float)hS) : 0.f;
            bc += s_above + FS + tie;
        }
        g_bc[b] = bc;
    }
}

// ==========================================================================
__global__ void k_out(float* __restrict__ out, int B) {
    int t = threadIdx.x;   // 64 threads
    float l = (t < B) ? g_bl[t] : 0.f;
    float c = (t < B) ? g_bc[t] : 0.f;
    float n = (t < B) ? (float)g_bn[t] : 0.f;
    #pragma unroll
    for (int o = 16; o; o >>= 1) {
        l += __shfl_down_sync(0xFFFFFFFFu, l, o);
        c += __shfl_down_sync(0xFFFFFFFFu, c, o);
        n += __shfl_down_sync(0xFFFFFFFFu, n, o);
    }
    __shared__ float sl[2], sc[2], sn[2];
    if ((t & 31) == 0) { sl[t >> 5] = l; sc[t >> 5] = c; sn[t >> 5] = n; }
    __syncthreads();
    if (t == 0) {
        float L = sl[0] + sl[1], C = sc[0] + sc[1], NN = sn[0] + sn[1];
        out[0] = L / NN;
        out[1] = C / NN;
    }
}

// ==========================================================================
extern "C" void kernel_launch(void* const* d_in, const int* in_sizes, int n_in,
                              void* d_out, int out_size)
{
    const float* loc    = (const float*)d_in[0];
    const float* conf   = (const float*)d_in[1];
    const float* priors = (const float*)d_in[2];
    const float* truths = (const float*)d_in[3];
    const int*   labels = (const int*)d_in[4];

    int P = in_sizes[2] / 4;
    int B = in_sizes[0] / (4 * P);
    int N = in_sizes[3] / (4 * B);

    int nA = (P + MROWS - 1) / MROWS;    // 32
    int nB = (P + LROWS - 1) / LROWS;    // 22

    dim3 fgrid(nA + nB, B);
    k_fused<<<fgrid, MTPB>>>(conf, priors, truths, P, N, nA);
    k_force<<<B, 32>>>(loc, conf, priors, truths, labels, P, N, nA);
    dim3 sgrid(NSB, B);
    k_hist<<<sgrid, 256>>>(loc, conf, priors, truths, labels, P, N);
    k_pick<<<B, 512>>>(P);
    k_fine<<<sgrid, 256>>>(P);
    k_batch<<<B, 512>>>(P);
    k_out<<<1, 64>>>((float*)d_out, B);
}

// round 17
// speedup vs baseline: 1.1000x; 1.1000x over previous
#include <cuda_runtime.h>
#include <cstdint>

#define MAXB   64
#define MAXN   16
#define NC     21
#define MTPB   256
#define MPPT   4
#define MROWS  (MTPB*MPPT)      // 1024
#define NABLK  24
#define MAXPP  24576
#define LTILE  256
#define LROWS  1024
#define NSB    8                // select slice-blocks per batch

// -------- scratch (__device__ globals; overwritten every launch) ----------
__device__ int                g_matchv[MAXB * MAXPP];
__device__ float              g_mine  [MAXB * MAXPP];
__device__ unsigned long long g_cK[MAXB * NABLK * MAXN];
__device__ float              g_partL[MAXB * NSB], g_partC[MAXB * NSB];
__device__ int                g_partN[MAXB * NSB];
__device__ int                g_ghist[MAXB * 1024];   // zeroed by k_fused
__device__ int                g_fhist[MAXB * 1024];   // zeroed by k_fused
__device__ float              g_fsum [MAXB * 1024];   // zeroed by k_fused
__device__ int                g_Bs[MAXB], g_krem[MAXB];
__device__ float              g_c0[MAXB];
__device__ float              g_aS[MAXB * NSB];
__device__ float              g_bl[MAXB], g_bc[MAXB];
__device__ int                g_bn[MAXB];

__device__ __forceinline__ float smooth_l1(float d) {
    float ad = fabsf(d);
    return (ad < 1.0f) ? 0.5f * d * d : ad - 0.5f;
}

__device__ __forceinline__ void cp16(float* dst, const float4* src) {
    unsigned s = (unsigned)__cvta_generic_to_shared(dst);
    asm volatile("cp.async.cg.shared.global [%0], [%1], 16;\n" :: "r"(s), "l"(src));
}

// ==========================================================================
// Fused: blockIdx.x < nA -> IoU matching (ALU); else -> lse stream (DRAM).
// R12 champion config: MPPT=4, LTILE=256 double-buffered, (256,5).
__global__ __launch_bounds__(256, 5) void k_fused(
    const float* __restrict__ conf,
    const float* __restrict__ priors,
    const float* __restrict__ truths,
    int P, int N, int nA)
{
    __shared__ __align__(16) float s_conf[2 * LTILE * NC];   // 43 KB
    __shared__ float4 s_t[MAXN];
    __shared__ float  s_area[MAXN];
    __shared__ unsigned long long s_best[MAXN];

    int b   = blockIdx.y;
    int tid = threadIdx.x;

    if (blockIdx.x < 16 && tid < 64) {
        int base = b * 1024 + blockIdx.x * 64 + tid;
        g_ghist[base] = 0;
        g_fhist[base] = 0;
        g_fsum [base] = 0.f;
    }

    if (blockIdx.x < nA) {
        // ================= MATCH PATH =================
        int p0   = blockIdx.x * MROWS;
        int lane = tid & 31;

        if (tid < MAXN) {
            s_best[tid] = 0ULL;
            if (tid < N) {
                float4 t = reinterpret_cast<const float4*>(truths)[b * N + tid];
                s_t[tid] = t;
                s_area[tid] = (t.z - t.x) * (t.w - t.y);
            }
        }
        __syncthreads();

        float px1[MPPT], py1[MPPT], px2[MPPT], py2[MPPT], ab[MPPT];
        #pragma unroll
        for (int i = 0; i < MPPT; ++i) {
            int p  = p0 + i * MTPB + tid;
            int pc = min(p, P - 1);         // clamp; dups lose ties via ~p
            float4 pr = reinterpret_cast<const float4*>(priors)[pc];
            float hx = pr.z * 0.5f, hy = pr.w * 0.5f;
            px1[i] = pr.x - hx; py1[i] = pr.y - hy;
            px2[i] = pr.x + hx; py2[i] = pr.y + hy;
            ab[i]  = pr.z * pr.w;
        }

        float bt[MPPT];
        int   bn[MPPT];
        #pragma unroll
        for (int i = 0; i < MPPT; ++i) { bt[i] = -1.f; bn[i] = 0; }

        #pragma unroll
        for (int n = 0; n < MAXN; ++n) {
            if (n < N) {
                float4 t = s_t[n];
                float sa = s_area[n];
                float biou = -1.f;
                int   bp   = 0x7FFFFFFF;
                #pragma unroll
                for (int i = 0; i < MPPT; ++i) {
                    float w = __saturatef(fminf(t.z, px2[i]) - fmaxf(t.x, px1[i]));
                    float h = __saturatef(fminf(t.w, py2[i]) - fmaxf(t.y, py1[i]));
                    float inter = w * h;
                    float uni   = sa + ab[i] - inter;
                    float iou   = __fdividef(inter, uni);
                    if (iou > bt[i]) { bt[i] = iou; bn[i] = n; }
                    if (iou > biou)  { biou = iou; bp = p0 + i * MTPB + tid; }
                }
                unsigned long long key =
                    ((unsigned long long)__float_as_uint(fmaxf(biou, 0.f)) << 32)
                    | (unsigned)~bp;
                #pragma unroll
                for (int o = 16; o; o >>= 1) {
                    unsigned long long ok = __shfl_down_sync(0xFFFFFFFFu, key, o);
                    key = (ok > key) ? ok : key;
                }
                if (lane == 0) atomicMax(&s_best[n], key);
            }
        }

        #pragma unroll
        for (int i = 0; i < MPPT; ++i) {
            int p = p0 + i * MTPB + tid;
            if (p < P) {
                int pos = (bt[i] >= 0.5f) ? 1 : 0;
                g_matchv[(size_t)b * P + p] = bn[i] | (pos << 31);
            }
        }
        __syncthreads();
        if (tid < MAXN)
            g_cK[((size_t)b * NABLK + blockIdx.x) * MAXN + tid] = s_best[tid];

    } else {
        // ================= LSE PATH (double-buffered) =================
        int bx   = blockIdx.x - nA;
        int r0   = bx * LROWS;
        int rows = min(LROWS, P - r0);
        int nt   = (rows + LTILE - 1) / LTILE;

        auto stage = [&](int t) {
            int tr = min(LTILE, rows - t * LTILE);
            int total = tr * NC;
            int n4 = total >> 2;
            const float* srcf = conf + ((size_t)b * P + r0 + t * LTILE) * NC;
            const float4* src4 = reinterpret_cast<const float4*>(srcf);
            float* dst = s_conf + (t & 1) * (LTILE * NC);
            for (int i = tid; i < n4; i += MTPB) cp16(dst + i * 4, src4 + i);
            for (int i = (n4 << 2) + tid; i < total; i += MTPB) dst[i] = srcf[i];
            asm volatile("cp.async.commit_group;\n");
        };

        stage(0);
        for (int t = 0; t < nt; ++t) {
            if (t + 1 < nt) {
                stage(t + 1);
                asm volatile("cp.async.wait_group 1;\n");
            } else {
                asm volatile("cp.async.wait_group 0;\n");
            }
            __syncthreads();

            int r = t * LTILE + tid;
            if (r < rows) {
                const float* row = s_conf + (t & 1) * (LTILE * NC) + tid * NC;
                float e0 = 0.f, e1 = 0.f, e2 = 0.f, e3 = 0.f;
                #pragma unroll
                for (int c = 0; c < NC; c += 4) {
                    e0 += __expf(row[c]);
                    if (c + 1 < NC) e1 += __expf(row[c + 1]);
                    if (c + 2 < NC) e2 += __expf(row[c + 2]);
                    if (c + 3 < NC) e3 += __expf(row[c + 3]);
                }
                float lse = __logf((e0 + e1) + (e2 + e3));
                g_mine[(size_t)b * P + r0 + r] = lse - row[0];   // >= 0
            }
            __syncthreads();
        }
    }
}

// ==========================================================================
// k_hist: 8 slice-blocks per batch, with the forced-prior pass FOLDED IN.
// Warp 0 of every block redundantly reduces g_cK -> forced table (identical
// everywhere); the block OWNING a forced prior's word zeroes it and adds the
// forced CE/loc/count to its own partials, all before a block-local barrier.
__global__ __launch_bounds__(256) void k_hist(
    const float* __restrict__ loc,
    const float* __restrict__ conf,
    const float* __restrict__ priors,
    const float* __restrict__ truths,
    const int*   __restrict__ labels,
    int P, int N, int nA)
{
    int b = blockIdx.y, s = blockIdx.x, tid = threadIdx.x;
    int w = tid >> 5, lane = tid & 31;

    __shared__ unsigned short s_h16[8 * 1024];   // 16 KB per-warp hists
    __shared__ float4 s_t[MAXN];
    __shared__ int    s_lab[MAXN];
    __shared__ float  s_rL[8], s_rC[8];
    __shared__ int    s_rN[8];
    __shared__ float  s_cL, s_cC;
    __shared__ int    s_cN;

    int n4 = P >> 2;
    int S4 = (n4 + NSB - 1) / NSB;
    int j0 = s * S4;
    int j1 = min(j0 + S4, n4);

    if (tid < N) {
        s_t[tid]   = reinterpret_cast<const float4*>(truths)[b * N + tid];
        s_lab[tid] = labels[b * N + tid];
    }
    if (tid == 0) { s_cL = 0.f; s_cC = 0.f; s_cN = 0; }
    {
        unsigned* z = reinterpret_cast<unsigned*>(s_h16);
        #pragma unroll
        for (int i = 0; i < 16; ++i) z[tid + i * 256] = 0u;
    }
    __syncthreads();   // s_t/s_lab visible to warp 0 below

    // ---- warp 0: forced priors (redundant table; block-local application) --
    if (w == 0) {
        unsigned long long best = 0ULL;
        if (lane < N)
            for (int j = 0; j < nA; ++j) {
                unsigned long long k2 = g_cK[((size_t)b * NABLK + j) * MAXN + lane];
                best = (k2 > best) ? k2 : best;
            }
        int fp = (lane < N) ? (int)~(unsigned)best : -1;
        bool valid = (lane < N);
        #pragma unroll
        for (int m = 0; m < MAXN; ++m) {
            int pm = __shfl_sync(0xFFFFFFFFu, fp, m);
            if (m < N && m > lane && pm == fp) valid = false;   // last truth wins
        }
        // ownership: the slice-block whose word range contains fp>>2
        int fj = fp >> 2;
        bool mine = valid &&
            ((fj >= j0 && fj < j1) || (s == NSB - 1 && fj >= n4));
        float dL = 0.f, dC = 0.f; int dN = 0;
        if (mine) {
            int p = fp;
            const float* crow = conf + ((size_t)b * P + p) * NC;
            float lse = g_mine[(size_t)b * P + p] + crow[0];
            float4 pr = reinterpret_cast<const float4*>(priors)[p];
            float4 ld = reinterpret_cast<const float4*>(loc)[(size_t)b * P + p];
            float4 tt = s_t[lane];
            dC += lse - crow[s_lab[lane] + 1];
            float gx = __fdividef((tt.x + tt.z) * 0.5f - pr.x, 0.1f * pr.z);
            float gy = __fdividef((tt.y + tt.w) * 0.5f - pr.y, 0.1f * pr.w);
            float gw = __logf(__fdividef(tt.z - tt.x, pr.z)) * 5.0f;
            float gh = __logf(__fdividef(tt.w - tt.y, pr.w)) * 5.0f;
            dL += smooth_l1(ld.x - gx) + smooth_l1(ld.y - gy)
                + smooth_l1(ld.z - gw) + smooth_l1(ld.w - gh);
            dN += 1;
            g_mine  [(size_t)b * P + p] = 0.f;   // exclude from mining
            g_matchv[(size_t)b * P + p] = 0;     // scan won't double-count
        }
        #pragma unroll
        for (int o = 16; o; o >>= 1) {
            dL += __shfl_down_sync(0xFFFFFFFFu, dL, o);
            dC += __shfl_down_sync(0xFFFFFFFFu, dC, o);
            dN += __shfl_down_sync(0xFFFFFFFFu, dN, o);
        }
        if (lane == 0) { s_cL = dL; s_cC = dC; s_cN = dN; }
    }
    __syncthreads();   // warp0's gmem zero-writes ordered before the scan

    int iters = (j1 - j0 + 255) / 256;

    const float4* mv  = reinterpret_cast<const float4*>(g_mine   + (size_t)b * P);
    const int4*   mm4 = reinterpret_cast<const int4*>  (g_matchv + (size_t)b * P);
    float4*       mw  = reinterpret_cast<float4*>      (g_mine   + (size_t)b * P);

    float L = 0.f, C = 0.f; int n = 0;
    unsigned short* myh = s_h16 + w * 1024;

    auto do_pos = [&](int mm, float& vref, int p, bool& chg) {
        if (mm < 0) {
            int bnn = mm & 0x7FFFFFFF;
            const float* crow = conf + ((size_t)b * P + p) * NC;
            float lse = vref + crow[0];
            C += lse - crow[s_lab[bnn] + 1];
            n++;
            float4 tt = s_t[bnn];
            float4 pr = reinterpret_cast<const float4*>(priors)[p];
            float gx = __fdividef((tt.x + tt.z) * 0.5f - pr.x, 0.1f * pr.z);
            float gy = __fdividef((tt.y + tt.w) * 0.5f - pr.y, 0.1f * pr.w);
            float gw = __logf(__fdividef(tt.z - tt.x, pr.z)) * 5.0f;
            float gh = __logf(__fdividef(tt.w - tt.y, pr.w)) * 5.0f;
            float4 ld = reinterpret_cast<const float4*>(loc)[(size_t)b * P + p];
            L += smooth_l1(ld.x - gx) + smooth_l1(ld.y - gy)
               + smooth_l1(ld.z - gw) + smooth_l1(ld.w - gh);
            vref = 0.f;
            chg = true;
        }
    };

    for (int i = 0; i < iters; ++i) {
        int j = j0 + i * 256 + tid;
        bool ok = (j < j1);
        float4 v = ok ? mv[j] : make_float4(0.f, 0.f, 0.f, 0.f);
        int4 m = ok ? mm4[j] : make_int4(0, 0, 0, 0);
        bool chg = false;
        int p = 4 * j;
        if (ok) {
            do_pos(m.x, v.x, p, chg);
            do_pos(m.y, v.y, p + 1, chg);
            do_pos(m.z, v.z, p + 2, chg);
            do_pos(m.w, v.w, p + 3, chg);
            if (chg) mw[j] = v;
        }
        unsigned vm = __ballot_sync(0xFFFFFFFFu, ok);
        {
            unsigned bin = __float_as_uint(v.x) >> 21;
            unsigned mk = __match_any_sync(0xFFFFFFFFu, bin) & vm;
            if (ok && lane == (__ffs(mk) - 1)) myh[bin] = (unsigned short)(myh[bin] + __popc(mk));
        }
        {
            unsigned bin = __float_as_uint(v.y) >> 21;
            unsigned mk = __match_any_sync(0xFFFFFFFFu, bin) & vm;
            if (ok && lane == (__ffs(mk) - 1)) myh[bin] = (unsigned short)(myh[bin] + __popc(mk));
        }
        {
            unsigned bin = __float_as_uint(v.z) >> 21;
            unsigned mk = __match_any_sync(0xFFFFFFFFu, bin) & vm;
            if (ok && lane == (__ffs(mk) - 1)) myh[bin] = (unsigned short)(myh[bin] + __popc(mk));
        }
        {
            unsigned bin = __float_as_uint(v.w) >> 21;
            unsigned mk = __match_any_sync(0xFFFFFFFFu, bin) & vm;
            if (ok && lane == (__ffs(mk) - 1)) myh[bin] = (unsigned short)(myh[bin] + __popc(mk));
        }
    }
    int tail = P & 3;
    if (s == NSB - 1 && tid < tail) {
        int p = (P & ~3) + tid;
        float vex = g_mine[(size_t)b * P + p];
        bool chg = false;
        do_pos(g_matchv[(size_t)b * P + p], vex, p, chg);
        if (chg) g_mine[(size_t)b * P + p] = 0.f;
        atomicAdd(&g_ghist[b * 1024 + (int)(__float_as_uint(vex) >> 21)], 1);
    }

    #pragma unroll
    for (int o = 16; o; o >>= 1) {
        L += __shfl_down_sync(0xFFFFFFFFu, L, o);
        C += __shfl_down_sync(0xFFFFFFFFu, C, o);
        n += __shfl_down_sync(0xFFFFFFFFu, n, o);
    }
    if (lane == 0) { s_rL[w] = L; s_rC[w] = C; s_rN[w] = n; }
    __syncthreads();
    if (tid == 0) {
        float Lt = s_cL, Ct = s_cC; int nt = s_cN;
        #pragma unroll
        for (int i = 0; i < 8; ++i) { Lt += s_rL[i]; Ct += s_rC[i]; nt += s_rN[i]; }
        g_partL[b * NSB + s] = Lt;
        g_partC[b * NSB + s] = Ct;
        g_partN[b * NSB + s] = nt;
    }

    {
        const unsigned* h32 = reinterpret_cast<const unsigned*>(s_h16);
        unsigned c0 = 0, c1 = 0, c2 = 0, c3 = 0;
        #pragma unroll
        for (int w2 = 0; w2 < 8; ++w2) {
            unsigned a = h32[w2 * 512 + 2 * tid];
            unsigned d = h32[w2 * 512 + 2 * tid + 1];
            c0 += a & 0xFFFFu; c1 += a >> 16;
            c2 += d & 0xFFFFu; c3 += d >> 16;
        }
        int base = b * 1024 + 4 * tid;
        if (c0) atomicAdd(&g_ghist[base],     (int)c0);
        if (c1) atomicAdd(&g_ghist[base + 1], (int)c1);
        if (c2) atomicAdd(&g_ghist[base + 2], (int)c2);
        if (c3) atomicAdd(&g_ghist[base + 3], (int)c3);
    }
}

// ==========================================================================
// 1024-bin suffix scan (512 threads, 2 bins/thread).
__device__ __forceinline__ void find_thresh1024(
    int l0, int l1, int k, int tid, int* s_wt, int* s_out)
{
    int w = tid >> 5, lane = tid & 31;
    int loc = l0 + l1;
    int incl = loc;
    #pragma unroll
    for (int o = 1; o < 32; o <<= 1) {
        int x = __shfl_up_sync(0xFFFFFFFFu, incl, o);
        if (lane >= o) incl += x;
    }
    int wsum = __shfl_sync(0xFFFFFFFFu, incl, 31);
    if (lane == 31) s_wt[w] = wsum;
    __syncthreads();
    int wa = 0;
    #pragma unroll
    for (int w2 = 0; w2 < 16; ++w2) if (w2 > w) wa += s_wt[w2];
    int above = wa + (wsum - incl);
    if (above < k && above + loc >= k) {
        if (above + l1 >= k) { s_out[0] = 2 * tid + 1; s_out[1] = above; }
        else                 { s_out[0] = 2 * tid;     s_out[1] = above + l1; }
    }
    __syncthreads();
}

// ==========================================================================
// k_pick: per batch — finalize partials, coarse threshold bin.
__global__ __launch_bounds__(512) void k_pick(int P) {
    int b = blockIdx.x, tid = threadIdx.x;
    int w = tid >> 5, lane = tid & 31;

    __shared__ int s_wt[16];
    __shared__ int s_out[2];
    __shared__ int s_k;

    if (tid == 0) { s_out[0] = 0; s_out[1] = 0; }
    if (w == 0) {
        float L = 0.f, C = 0.f; int n = 0;
        if (lane < NSB) {
            L = g_partL[b * NSB + lane];
            C = g_partC[b * NSB + lane];
            n = g_partN[b * NSB + lane];
        }
        #pragma unroll
        for (int o = 16; o; o >>= 1) {
            L += __shfl_down_sync(0xFFFFFFFFu, L, o);
            C += __shfl_down_sync(0xFFFFFFFFu, C, o);
            n += __shfl_down_sync(0xFFFFFFFFu, n, o);
        }
        if (lane == 0) {
            g_bl[b] = L; g_c0[b] = C; g_bn[b] = n;
            s_k = (n > 0) ? min(3 * n, P - 1) : 0;
        }
    }
    __syncthreads();
    int k = s_k;

    int l0 = g_ghist[b * 1024 + 2 * tid];
    int l1 = g_ghist[b * 1024 + 2 * tid + 1];
    find_thresh1024(l0, l1, k, tid, s_wt, s_out);

    if (tid == 0) {
        if (k > 0) { g_Bs[b] = s_out[0]; g_krem[b] = k - s_out[1]; }
        else       { g_Bs[b] = 1024;     g_krem[b] = 0; }
    }
}

// ==========================================================================
// k_fine: 8 slice-blocks per batch. Exact sum of values above coarse bin;
// tie-bin values get fine count + sum via gmem atomics.
__global__ __launch_bounds__(256) void k_fine(int P) {
    int b = blockIdx.y, s = blockIdx.x, tid = threadIdx.x;
    int w = tid >> 5, lane = tid & 31;

    __shared__ float s_r[8];

    int Bs = g_Bs[b];
    int n4 = P >> 2;
    int S4 = (n4 + NSB - 1) / NSB;
    int j0 = s * S4;
    int j1 = min(j0 + S4, n4);

    const float4* mv = reinterpret_cast<const float4*>(g_mine + (size_t)b * P);
    float S = 0.f;

    auto proc = [&](float v) {
        int bin = (int)(__float_as_uint(v) >> 21);
        if (bin > Bs) {
            S += v;
        } else if (bin == Bs) {
            int fb = (int)((__float_as_uint(v) >> 11) & 1023u);
            atomicAdd(&g_fhist[b * 1024 + fb], 1);
            atomicAdd(&g_fsum [b * 1024 + fb], v);
        }
    };

    for (int j = j0 + tid; j < j1; j += 256) {
        float4 v = mv[j];
        proc(v.x); proc(v.y); proc(v.z); proc(v.w);
    }
    int tail = P & 3;
    if (s == NSB - 1 && tid < tail)
        proc(g_mine[(size_t)b * P + (P & ~3) + tid]);

    #pragma unroll
    for (int o = 16; o; o >>= 1) S += __shfl_down_sync(0xFFFFFFFFu, S, o);
    if (lane == 0) s_r[w] = S;
    __syncthreads();
    if (tid == 0) {
        float T = 0.f;
        #pragma unroll
        for (int i = 0; i < 8; ++i) T += s_r[i];
        g_aS[b * NSB + s] = T;
    }
}

// ==========================================================================
// k_batch: per batch — fine threshold, tie term via bin mean, total loss_c.
__global__ __launch_bounds__(512) void k_batch(int P) {
    int b = blockIdx.x, tid = threadIdx.x;
    int w = tid >> 5, lane = tid & 31;

    __shared__ int   s_wt[16];
    __shared__ int   s_out[2];
    __shared__ float s_r[16];
    __shared__ float s_above;
    __shared__ int   s_krem;

    if (w == 0) {
        float a = (lane < NSB) ? g_aS[b * NSB + lane] : 0.f;
        #pragma unroll
        for (int o = 16; o; o >>= 1) a += __shfl_down_sync(0xFFFFFFFFu, a, o);
        if (lane == 0) {
            s_above = a;
            s_krem  = g_krem[b];
            s_out[0] = 0; s_out[1] = 0;
        }
    }
    __syncthreads();
    int krem = s_krem;

    int l0 = g_fhist[b * 1024 + 2 * tid];
    int l1 = g_fhist[b * 1024 + 2 * tid + 1];
    find_thresh1024(l0, l1, krem, tid, s_wt, s_out);
    int Ss = s_out[0];
    int c2 = s_out[1];

    float fs = 0.f;
    if (krem > 0) {
        if (2 * tid     > Ss) fs += g_fsum[b * 1024 + 2 * tid];
        if (2 * tid + 1 > Ss) fs += g_fsum[b * 1024 + 2 * tid + 1];
    }
    #pragma unroll
    for (int o = 16; o; o >>= 1) fs += __shfl_down_sync(0xFFFFFFFFu, fs, o);
    if (lane == 0) s_r[w] = fs;
    __syncthreads();

    if (tid == 0) {
        float FS = 0.f;
        #pragma unroll
        for (int i = 0; i < 16; ++i) FS += s_r[i];
        float bc = g_c0[b];
        if (krem > 0) {
            int   hS = g_fhist[b * 1024 + Ss];
            float sS = g_fsum [b * 1024 + Ss];
            int  rem = krem - c2;
            float tie = (hS > 0) ? (float)rem * (sS / (float)hS) : 0.f;
            bc += s_above + FS + tie;
        }
        g_bc[b] = bc;
    }
}

// ==========================================================================
__global__ void k_out(float* __restrict__ out, int B) {
    int t = threadIdx.x;   // 64 threads
    float l = (t < B) ? g_bl[t] : 0.f;
    float c = (t < B) ? g_bc[t] : 0.f;
    float n = (t < B) ? (float)g_bn[t] : 0.f;
    #pragma unroll
    for (int o = 16; o; o >>= 1) {
        l += __shfl_down_sync(0xFFFFFFFFu, l, o);
        c += __shfl_down_sync(0xFFFFFFFFu, c, o);
        n += __shfl_down_sync(0xFFFFFFFFu, n, o);
    }
    __shared__ float sl[2], sc[2], sn[2];
    if ((t & 31) == 0) { sl[t >> 5] = l; sc[t >> 5] = c; sn[t >> 5] = n; }
    __syncthreads();
    if (t == 0) {
        float L = sl[0] + sl[1], C = sc[0] + sc[1], NN = sn[0] + sn[1];
        out[0] = L / NN;
        out[1] = C / NN;
    }
}

// ==========================================================================
extern "C" void kernel_launch(void* const* d_in, const int* in_sizes, int n_in,
                              void* d_out, int out_size)
{
    const float* loc    = (const float*)d_in[0];
    const float* conf   = (const float*)d_in[1];
    const float* priors = (const float*)d_in[2];
    const float* truths = (const float*)d_in[3];
    const int*   labels = (const int*)d_in[4];

    int P = in_sizes[2] / 4;
    int B = in_sizes[0] / (4 * P);
    int N = in_sizes[3] / (4 * B);

    int nA = (P + MROWS - 1) / MROWS;    // 24
    int nB = (P + LROWS - 1) / LROWS;    // 24

    dim3 fgrid(nA + nB, B);
    k_fused<<<fgrid, MTPB>>>(conf, priors, truths, P, N, nA);
    dim3 sgrid(NSB, B);
    k_hist<<<sgrid, 256>>>(loc, conf, priors, truths, labels, P, N, nA);
    k_pick<<<B, 512>>>(P);
    k_fine<<<sgrid, 256>>>(P);
    k_batch<<<B, 512>>>(P);
    k_out<<<1, 64>>>((float*)d_out, B);
}